// round 1
// baseline (speedup 1.0000x reference)
#include <cuda_runtime.h>

// Problem constants: S=7, B=2, C=20, E=30, BATCH=16384
// cells = 16384*7*7 = 802816, each cell: 30 floats pred + 30 floats target.

__global__ void zero_out_kernel(float* out) {
    if (threadIdx.x < 5) out[threadIdx.x] = 0.0f;
}

__global__ void __launch_bounds__(256) yolo_loss_kernel(
    const float* __restrict__ pred,
    const float* __restrict__ tgt,
    float* __restrict__ out,
    int ncells)
{
    float lxy = 0.f, lwh = 0.f, lobj = 0.f, lnoobj = 0.f, lcls = 0.f;

    int cell = blockIdx.x * blockDim.x + threadIdx.x;
    if (cell < ncells) {
        // 30 floats per cell => 15 float2 (cell*120 bytes is 8B-aligned)
        const float2* p2 = reinterpret_cast<const float2*>(pred) + (long long)cell * 15;
        const float2* t2 = reinterpret_cast<const float2*>(tgt)  + (long long)cell * 15;

        float p[30], t[30];
        #pragma unroll
        for (int i = 0; i < 15; i++) {
            float2 v = p2[i]; p[2*i] = v.x; p[2*i+1] = v.y;
            float2 u = t2[i]; t[2*i] = u.x; t[2*i+1] = u.y;
        }

        float m  = (t[4] > 0.0f) ? 1.0f : 0.0f;  // conf is exactly 0.0 or 1.0
        float nm = 1.0f - m;

        // IoU of each pred box vs target box 0
        float tx0 = t[0], ty0 = t[1], tx1 = t[2], ty1 = t[3];
        float a2 = (tx1 - tx0) * (ty1 - ty0);
        float iou[2];
        #pragma unroll
        for (int b = 0; b < 2; b++) {
            const float* pb = &p[5 * b];
            float ltx = fmaxf(pb[0], tx0), lty = fmaxf(pb[1], ty0);
            float rbx = fminf(pb[2], tx1), rby = fminf(pb[3], ty1);
            float w = fmaxf(rbx - ltx, 0.0f);
            float h = fmaxf(rby - lty, 0.0f);
            float inter = w * h;
            float a1 = (pb[2] - pb[0]) * (pb[3] - pb[1]);
            iou[b] = inter / (a1 + a2 - inter);
        }
        // jnp.argmax: first index of max -> strict greater-than for box 1
        int idx = (iou[1] > iou[0]) ? 1 : 0;
        float maxiou = fmaxf(iou[0], iou[1]);

        const float* pb = &p[5 * idx];
        const float* tb = &t[5 * idx];

        float dx = pb[0] - tb[0], dy = pb[1] - tb[1];
        lxy = m * (dx * dx + dy * dy);

        float dw = sqrtf(pb[2]) - sqrtf(tb[2]);
        float dh = sqrtf(pb[3]) - sqrtf(tb[3]);
        lwh = m * (dw * dw + dh * dh);

        float dobj = pb[4] - maxiou;
        lobj = m * dobj * dobj;

        float d4 = p[4] - t[4], d9 = p[9] - t[9];
        lnoobj = nm * (d4 * d4 + d9 * d9);

        float cs = 0.0f;
        #pragma unroll
        for (int c = 10; c < 30; c++) {
            float d = p[c] - t[c];
            cs = fmaf(d, d, cs);
        }
        lcls = m * cs;
    }

    // ---- block reduction: warp shuffle then shared ----
    #pragma unroll
    for (int off = 16; off > 0; off >>= 1) {
        lxy    += __shfl_down_sync(0xffffffff, lxy,    off);
        lwh    += __shfl_down_sync(0xffffffff, lwh,    off);
        lobj   += __shfl_down_sync(0xffffffff, lobj,   off);
        lnoobj += __shfl_down_sync(0xffffffff, lnoobj, off);
        lcls   += __shfl_down_sync(0xffffffff, lcls,   off);
    }

    __shared__ float smem[5][8];
    int wid  = threadIdx.x >> 5;
    int lane = threadIdx.x & 31;
    if (lane == 0) {
        smem[0][wid] = lxy;
        smem[1][wid] = lwh;
        smem[2][wid] = lobj;
        smem[3][wid] = lnoobj;
        smem[4][wid] = lcls;
    }
    __syncthreads();

    if (threadIdx.x < 5) {
        float s = 0.f;
        #pragma unroll
        for (int w = 0; w < 8; w++) s += smem[threadIdx.x][w];
        atomicAdd(&out[threadIdx.x], s);
    }
}

extern "C" void kernel_launch(void* const* d_in, const int* in_sizes, int n_in,
                              void* d_out, int out_size) {
    const float* pred = (const float*)d_in[0];
    const float* tgt  = (const float*)d_in[1];
    float* out = (float*)d_out;

    int ncells = in_sizes[0] / 30;  // 16384*7*7 = 802816

    zero_out_kernel<<<1, 32>>>(out);

    int threads = 256;
    int blocks = (ncells + threads - 1) / threads;
    yolo_loss_kernel<<<blocks, threads>>>(pred, tgt, out, ncells);
}